// round 9
// baseline (speedup 1.0000x reference)
#include <cuda_runtime.h>
#include <cstdint>

// CondConv3d via tf32 mma.sync implicit GEMM (tensor pipe; compute_103-safe).
// Round 9: 2 CTAs/SM. Per-dz W staging (9 taps, 41.5KB) + 4-row h tile
// (xT 52.2KB) => 93.7KB smem/CTA. Warp = (h row, m half): M32 x N32.
//
// out[b] = s[b] * (conv3d(x[b], Wsum) + bias_sum)

#define B_ 8
#define CIN 32
#define COUT 32
#define DD 16
#define HH_ 64
#define WW 64

#define TH 4                        // output h rows per block
#define XROWS (TH + 2)              // 6 tile rows
#define ROW_PITCH 68                // 64 data + 2 zero + 2 pad
#define XT_PITCH (XROWS * ROW_PITCH)   // 408 floats per c; 408 % 32 == 24
#define XT_FLOATS (CIN * XT_PITCH)  // 13056
#define WPC 36                      // W pitch over c (conflict-free)
#define W_TAP (COUT * WPC)          // 1152 floats per tap
#define W_DZ (9 * W_TAP)            // 10368 floats per dz stage
#define W_FLOATS (27 * W_TAP)       // 31104 (in gmem)
#define OFF_XT 0
#define OFF_W XT_FLOATS
#define SMEM_FLOATS (XT_FLOATS + W_DZ)   // 23424 -> 93696 B

__device__ float g_wt[W_FLOATS];    // [tap][o][c36], expert-summed, tf32-rounded
__device__ float g_bias[COUT];
__device__ float g_s[B_];

__device__ __forceinline__ float to_tf32(float v) {
    uint32_t u;
    asm("cvt.rna.tf32.f32 %0, %1;" : "=r"(u) : "f"(v));
    return __uint_as_float(u);
}

__global__ void prep_kernel(const float* __restrict__ weight,
                            const float* __restrict__ bias,
                            const float* __restrict__ rw) {
    int idx = blockIdx.x * 256 + threadIdx.x;
    if (idx < W_FLOATS) {
        int t = idx / W_TAP;
        int rem = idx % W_TAP;
        int o = rem / WPC;
        int c = rem % WPC;
        float v = 0.f;
        if (c < 32) {
            #pragma unroll
            for (int e = 0; e < 8; e++)
                v += weight[((e * 32 + o) * 32 + c) * 27 + t];
            v = to_tf32(v);
        }
        g_wt[idx] = v;
    }
    if (blockIdx.x == 0) {
        int tid = threadIdx.x;
        if (tid < COUT) {
            float s = 0.f;
            #pragma unroll
            for (int e = 0; e < 8; e++) s += bias[e * COUT + tid];
            g_bias[tid] = s;
        } else if (tid < COUT + B_) {
            int b = tid - COUT;
            float s = 0.f;
            #pragma unroll
            for (int e = 0; e < 8; e++) s += rw[b * 8 + e];
            g_s[b] = s;
        }
    }
}

// ---- cp.async helpers ----
__device__ __forceinline__ void cp16_zfill(uint32_t saddr, const float* g, int srcsz) {
    asm volatile("cp.async.cg.shared.global [%0], [%1], 16, %2;"
                 :: "r"(saddr), "l"(g), "r"(srcsz));
}
__device__ __forceinline__ void cp16(uint32_t saddr, const float* g) {
    asm volatile("cp.async.cg.shared.global [%0], [%1], 16;"
                 :: "r"(saddr), "l"(g));
}
__device__ __forceinline__ void cp_commit() { asm volatile("cp.async.commit_group;"); }
__device__ __forceinline__ void cp_wait0()  { asm volatile("cp.async.wait_group 0;"); }

__device__ __forceinline__ void mma_tf32(float* c, uint32_t a0, uint32_t a1,
                                         uint32_t a2, uint32_t a3,
                                         uint32_t b0, uint32_t b1) {
    asm volatile("mma.sync.aligned.m16n8k8.row.col.f32.tf32.tf32.f32 "
                 "{%0,%1,%2,%3}, {%4,%5,%6,%7}, {%8,%9}, {%0,%1,%2,%3};"
                 : "+f"(c[0]), "+f"(c[1]), "+f"(c[2]), "+f"(c[3])
                 : "r"(a0), "r"(a1), "r"(a2), "r"(a3), "r"(b0), "r"(b1));
}

extern __shared__ float smem[];

__global__ __launch_bounds__(256, 2) void conv_kernel(const float* __restrict__ x,
                                                      float* __restrict__ out) {
    const int tid  = threadIdx.x;
    const int wid  = tid >> 5;
    const int lane = tid & 31;
    const int g    = lane >> 2;        // fragment groupID
    const int tig  = lane & 3;         // fragment threadID-in-group
    const int hrow   = wid & 3;        // output h row within tile
    const int mhalf  = wid >> 2;       // w half (0: w0..31, 1: w32..63)

    const int htile = blockIdx.x;      // 4 h rows each
    const int d     = blockIdx.y;
    const int b     = blockIdx.z;
    const int h0    = htile * TH;

    const float* __restrict__ xb = x + (size_t)b * CIN * DD * HH_ * WW;
    const uint32_t smem_u = (uint32_t)__cvta_generic_to_shared(smem);

    // ---- init permanent zero slots (ww3 = 64..67 of every row) ----
    for (int i = tid; i < CIN * XROWS * 4; i += 256) {
        int c = i / (XROWS * 4);
        int r = (i / 4) % XROWS;
        int z = i & 3;
        smem[OFF_XT + c * XT_PITCH + r * ROW_PITCH + 64 + z] = 0.f;
    }

    // ---- xT staging: 32c x 6 rows x 16 chunks = 3072 cp16 (12/thread) ----
    const int sc = tid >> 3;           // c 0..31
    const int s8 = tid & 7;
    auto stage_x = [&](int dz) {
        int gd = d + dz - 1;
        bool dok = (gd >= 0) && (gd < DD);
        const float* base = xb + ((size_t)sc * DD + (dok ? gd : 0)) * HH_ * WW;
        #pragma unroll
        for (int j = 0; j < 12; j++) {
            int slot = s8 + 8 * j;     // 0..95
            int hh2  = slot >> 4;      // row 0..5
            int q    = slot & 15;      // 4-float chunk
            int gh = h0 + hh2 - 1;
            bool ok = dok && (gh >= 0) && (gh < HH_);
            uint32_t dst = smem_u +
                (OFF_XT + sc * XT_PITCH + hh2 * ROW_PITCH + q * 4) * 4;
            cp16_zfill(dst, base + (ok ? gh : 0) * WW + q * 4, ok ? 16 : 0);
        }
    };
    // ---- W staging for one dz: 2592 float4 (11/thread) ----
    auto stage_w = [&](int dz) {
        const float* src = g_wt + dz * W_DZ;
        #pragma unroll
        for (int k = 0; k < 11; k++) {
            int idx = tid + 256 * k;
            if (idx < W_DZ / 4)
                cp16(smem_u + (OFF_W + idx * 4) * 4, src + idx * 4);
        }
    };

    // ---- accumulators: C[mi][ni][4] (M32 x N32 per warp) ----
    float acc[2][4][4];
    #pragma unroll
    for (int mi = 0; mi < 2; mi++)
        #pragma unroll
        for (int ni = 0; ni < 4; ni++)
            #pragma unroll
            for (int r = 0; r < 4; r++) acc[mi][ni][r] = 0.f;

    const uint32_t* xtu = reinterpret_cast<const uint32_t*>(smem + OFF_XT);
    const uint32_t* wtu = reinterpret_cast<const uint32_t*>(smem + OFF_W);

    #pragma unroll 1
    for (int dz = 0; dz < 3; dz++) {
        stage_x(dz);
        stage_w(dz);
        cp_commit();
        cp_wait0();
        __syncthreads();

        #pragma unroll 1
        for (int t2 = 0; t2 < 9; t2++) {
            const int kh = t2 / 3;
            const int kwm1 = t2 % 3 - 1;
            const int hh2 = hrow + kh;                      // 0..5
            const uint32_t* xrow = xtu + hh2 * ROW_PITCH;
            const uint32_t* wtap = wtu + t2 * W_TAP;
            #pragma unroll
            for (int kc = 0; kc < 4; kc++) {
                const int c0 = kc * 8 + tig;
                uint32_t b0[4], b1[4];
                #pragma unroll
                for (int ni = 0; ni < 4; ni++) {
                    const uint32_t* wb = wtap + (ni * 8 + g) * WPC + c0;
                    b0[ni] = wb[0];
                    b1[ni] = wb[4];
                }
                #pragma unroll
                for (int mi = 0; mi < 2; mi++) {
                    int win = mhalf * 32 + mi * 16 + g + kwm1;
                    int r0 = (win < 0) ? 65 : win;          // left halo -> zero
                    int r1 = win + 8;                       // 64 -> zero slot
                    const uint32_t* xc = xrow + c0 * XT_PITCH;
                    uint32_t a0 = xc[r0];
                    uint32_t a1 = xc[r1];
                    uint32_t a2 = xc[r0 + 4 * XT_PITCH];
                    uint32_t a3 = xc[r1 + 4 * XT_PITCH];
                    #pragma unroll
                    for (int ni = 0; ni < 4; ni++)
                        mma_tf32(acc[mi][ni], a0, a1, a2, a3, b0[ni], b1[ni]);
                }
            }
        }
        __syncthreads();   // reads done before next dz overwrites buffers
    }

    // ---- epilogue: out[b][o][d][h][w] = s*(acc + bias[o]) ----
    const float sb = g_s[b];
    const int h = h0 + hrow;
    #pragma unroll
    for (int ni = 0; ni < 4; ni++) {
        const int o0 = ni * 8 + 2 * tig;
        const float bs0 = g_bias[o0];
        const float bs1 = g_bias[o0 + 1];
        float* p0 = out + (((size_t)(b * COUT + o0) * DD + d) * HH_ + h) * WW;
        float* p1 = out + (((size_t)(b * COUT + o0 + 1) * DD + d) * HH_ + h) * WW;
        #pragma unroll
        for (int mi = 0; mi < 2; mi++) {
            const int w = mhalf * 32 + mi * 16 + g;
            p0[w]     = sb * (acc[mi][ni][0] + bs0);
            p1[w]     = sb * (acc[mi][ni][1] + bs1);
            p0[w + 8] = sb * (acc[mi][ni][2] + bs0);
            p1[w + 8] = sb * (acc[mi][ni][3] + bs1);
        }
    }
}

extern "C" void kernel_launch(void* const* d_in, const int* in_sizes, int n_in,
                              void* d_out, int out_size) {
    // x: 16777216, rw: 64, weight: 221184, bias: 256
    const float *x = nullptr, *rw = nullptr, *wt = nullptr, *bi = nullptr;
    for (int i = 0; i < n_in; i++) {
        if (in_sizes[i] == 16777216)     x  = (const float*)d_in[i];
        else if (in_sizes[i] == 221184)  wt = (const float*)d_in[i];
        else if (in_sizes[i] == 256)     bi = (const float*)d_in[i];
        else if (in_sizes[i] == 64)      rw = (const float*)d_in[i];
    }
    float* out = (float*)d_out;

    cudaFuncSetAttribute(conv_kernel,
                         cudaFuncAttributeMaxDynamicSharedMemorySize,
                         SMEM_FLOATS * 4);

    prep_kernel<<<(W_FLOATS + 255) / 256, 256>>>(wt, bi, rw);

    dim3 grid(HH_ / TH, DD, B_);   // (16, 16, 8) = 2048 blocks
    conv_kernel<<<grid, 256, SMEM_FLOATS * 4>>>(x, out);
}

// round 10
// speedup vs baseline: 1.1349x; 1.1349x over previous
#include <cuda_runtime.h>
#include <cstdint>

// CondConv3d via tf32 mma.sync implicit GEMM (tensor pipe; compute_103-safe).
// Round 10: R8's fat tile (TH=8, warp=row, M64xN32 per warp, 1.5 LDS-wf/MMA)
// AND 2 CTAs/SM, by staging W in (dz,kh) chunks of 3 taps, double-buffered.
// smem = xT 87040B + 2x13824B W = 114688B -> exactly 2 CTAs/SM.
//
// out[b] = s[b] * (conv3d(x[b], Wsum) + bias_sum)

#define B_ 8
#define CIN 32
#define COUT 32
#define DD 16
#define HH_ 64
#define WW 64

#define TH 8                        // output h rows per block
#define XROWS (TH + 2)              // 10
#define ROW_PITCH 68                // 64 data + 2 zero + 2 pad
#define XT_PITCH (XROWS * ROW_PITCH)   // 680; 680 % 32 == 8 (conflict-free)
#define XT_FLOATS (CIN * XT_PITCH)  // 21760
#define WPC 36                      // W pitch over c (bank = 4g+tig, distinct)
#define W_TAP (COUT * WPC)          // 1152 floats per tap
#define W_CHUNK (3 * W_TAP)         // 3456 floats per (dz,kh) chunk
#define W_FLOATS (27 * W_TAP)       // 31104 (gmem)
#define OFF_XT 0
#define OFF_W XT_FLOATS
#define SMEM_FLOATS (XT_FLOATS + 2 * W_CHUNK)   // 28672 floats = 114688 B

__device__ float g_wt[W_FLOATS];    // [tap][o][c36], expert-summed, tf32-rounded
__device__ float g_bias[COUT];
__device__ float g_s[B_];

__device__ __forceinline__ float to_tf32(float v) {
    uint32_t u;
    asm("cvt.rna.tf32.f32 %0, %1;" : "=r"(u) : "f"(v));
    return __uint_as_float(u);
}

__global__ void prep_kernel(const float* __restrict__ weight,
                            const float* __restrict__ bias,
                            const float* __restrict__ rw) {
    int idx = blockIdx.x * 256 + threadIdx.x;
    if (idx < W_FLOATS) {
        int t = idx / W_TAP;
        int rem = idx % W_TAP;
        int o = rem / WPC;
        int c = rem % WPC;
        float v = 0.f;
        if (c < 32) {
            #pragma unroll
            for (int e = 0; e < 8; e++)
                v += weight[((e * 32 + o) * 32 + c) * 27 + t];
            v = to_tf32(v);
        }
        g_wt[idx] = v;
    }
    if (blockIdx.x == 0) {
        int tid = threadIdx.x;
        if (tid < COUT) {
            float s = 0.f;
            #pragma unroll
            for (int e = 0; e < 8; e++) s += bias[e * COUT + tid];
            g_bias[tid] = s;
        } else if (tid < COUT + B_) {
            int b = tid - COUT;
            float s = 0.f;
            #pragma unroll
            for (int e = 0; e < 8; e++) s += rw[b * 8 + e];
            g_s[b] = s;
        }
    }
}

// ---- cp.async helpers ----
__device__ __forceinline__ void cp16_zfill(uint32_t saddr, const float* g, int srcsz) {
    asm volatile("cp.async.cg.shared.global [%0], [%1], 16, %2;"
                 :: "r"(saddr), "l"(g), "r"(srcsz));
}
__device__ __forceinline__ void cp16(uint32_t saddr, const float* g) {
    asm volatile("cp.async.cg.shared.global [%0], [%1], 16;"
                 :: "r"(saddr), "l"(g));
}
__device__ __forceinline__ void cp_commit() { asm volatile("cp.async.commit_group;"); }
__device__ __forceinline__ void cp_wait0()  { asm volatile("cp.async.wait_group 0;"); }

__device__ __forceinline__ void mma_tf32(float* c, uint32_t a0, uint32_t a1,
                                         uint32_t a2, uint32_t a3,
                                         uint32_t b0, uint32_t b1) {
    asm volatile("mma.sync.aligned.m16n8k8.row.col.f32.tf32.tf32.f32 "
                 "{%0,%1,%2,%3}, {%4,%5,%6,%7}, {%8,%9}, {%0,%1,%2,%3};"
                 : "+f"(c[0]), "+f"(c[1]), "+f"(c[2]), "+f"(c[3])
                 : "r"(a0), "r"(a1), "r"(a2), "r"(a3), "r"(b0), "r"(b1));
}

extern __shared__ float smem[];

__global__ __launch_bounds__(256, 2) void conv_kernel(const float* __restrict__ x,
                                                      float* __restrict__ out) {
    const int tid  = threadIdx.x;
    const int wid  = tid >> 5;         // warp = one output h row (0..7)
    const int lane = tid & 31;
    const int g    = lane >> 2;        // fragment groupID
    const int tig  = lane & 3;         // fragment threadID-in-group

    const int htile = blockIdx.x;      // 8 h rows each
    const int d     = blockIdx.y;
    const int b     = blockIdx.z;
    const int h0    = htile * TH;

    const float* __restrict__ xb = x + (size_t)b * CIN * DD * HH_ * WW;
    const uint32_t smem_u = (uint32_t)__cvta_generic_to_shared(smem);

    // ---- init permanent zero slots (ww3 = 64..67 of every row) ----
    for (int i = tid; i < CIN * XROWS * 4; i += 256) {
        int c = i / (XROWS * 4);
        int r = (i / 4) % XROWS;
        int z = i & 3;
        smem[OFF_XT + c * XT_PITCH + r * ROW_PITCH + 64 + z] = 0.f;
    }

    // ---- xT staging: 32c x 10 rows x 16 chunks = 5120 cp16 (20/thread) ----
    const int sc = tid >> 3;           // c 0..31
    const int s8 = tid & 7;
    auto stage_x = [&](int dz) {
        int gd = d + dz - 1;
        bool dok = (gd >= 0) && (gd < DD);
        const float* base = xb + ((size_t)sc * DD + (dok ? gd : 0)) * HH_ * WW;
        #pragma unroll
        for (int j = 0; j < 20; j++) {
            int slot = s8 + 8 * j;     // 0..159
            int hh2  = slot >> 4;      // row 0..9
            int q    = slot & 15;      // 4-float chunk
            int gh = h0 + hh2 - 1;
            bool ok = dok && (gh >= 0) && (gh < HH_);
            uint32_t dst = smem_u +
                (OFF_XT + sc * XT_PITCH + hh2 * ROW_PITCH + q * 4) * 4;
            cp16_zfill(dst, base + (ok ? gh : 0) * WW + q * 4, ok ? 16 : 0);
        }
    };
    // ---- W chunk staging: 864 float4 (3.4/thread) into buffer bf ----
    auto stage_w = [&](int chunk, int bf) {
        const float* src = g_wt + chunk * W_CHUNK;
        uint32_t dst = smem_u + (OFF_W + bf * W_CHUNK) * 4;
        #pragma unroll
        for (int k = 0; k < 4; k++) {
            int idx = tid + 256 * k;
            if (idx < W_CHUNK / 4)
                cp16(dst + idx * 16, src + idx * 4);
        }
    };

    // ---- accumulators: C[mi][ni][4] (M64 x N32 per warp) ----
    float acc[4][4][4];
    #pragma unroll
    for (int mi = 0; mi < 4; mi++)
        #pragma unroll
        for (int ni = 0; ni < 4; ni++)
            #pragma unroll
            for (int r = 0; r < 4; r++) acc[mi][ni][r] = 0.f;

    const uint32_t* xtu = reinterpret_cast<const uint32_t*>(smem + OFF_XT);
    const uint32_t* wtu = reinterpret_cast<const uint32_t*>(smem + OFF_W);

    // ---- prologue ----
    stage_w(0, 0);
    stage_x(0);
    cp_commit();
    cp_wait0();
    __syncthreads();

    #pragma unroll 1
    for (int chunk = 0; chunk < 9; chunk++) {
        const int dz = chunk / 3;
        const int kh = chunk % 3;
        const int bf = chunk & 1;

        // prefetch next W chunk into the other buffer (overlaps compute)
        if (chunk < 8) {
            stage_w(chunk + 1, bf ^ 1);
            cp_commit();
        }

        // ---- compute this (dz,kh) chunk: 3 kw x 4 kc x 16 MMAs ----
        const int hh2 = wid + kh;                       // 0..9
        const uint32_t* xrow = xtu + hh2 * ROW_PITCH;
        const uint32_t* wbuf = wtu + bf * W_CHUNK;
        #pragma unroll
        for (int kw = 0; kw < 3; kw++) {
            const int kwm1 = kw - 1;
            const uint32_t* wtap = wbuf + kw * W_TAP;
            #pragma unroll
            for (int kc = 0; kc < 4; kc++) {
                const int c0 = kc * 8 + tig;
                uint32_t b0[4], b1[4];
                #pragma unroll
                for (int ni = 0; ni < 4; ni++) {
                    const uint32_t* wb = wtap + (ni * 8 + g) * WPC + c0;
                    b0[ni] = wb[0];
                    b1[ni] = wb[4];
                }
                #pragma unroll
                for (int mi = 0; mi < 4; mi++) {
                    int win = mi * 16 + g + kwm1;
                    int r0 = (win < 0) ? 65 : win;      // left halo -> zero slot
                    int r1 = win + 8;                   // 64 -> zero slot
                    const uint32_t* xc = xrow + c0 * XT_PITCH;
                    uint32_t a0 = xc[r0];
                    uint32_t a1 = xc[r1];
                    uint32_t a2 = xc[r0 + 4 * XT_PITCH];
                    uint32_t a3 = xc[r1 + 4 * XT_PITCH];
                    #pragma unroll
                    for (int ni = 0; ni < 4; ni++)
                        mma_tf32(acc[mi][ni], a0, a1, a2, a3, b0[ni], b1[ni]);
                }
            }
        }

        // ---- chunk boundary: make prefetched W visible; restage xT at dz edge ----
        if (kh == 2 && dz < 2) {
            __syncthreads();           // all reads of xT done before overwrite
            stage_x(dz + 1);
            cp_commit();
            cp_wait0();                // waits xT + pending W prefetch
            __syncthreads();
        } else if (chunk < 8) {
            cp_wait0();                // W prefetch complete (thread-local)
            __syncthreads();           // visible to all warps
        }
    }

    // ---- epilogue: out[b][o][d][h][w] = s*(acc + bias[o]) ----
    const float sb = g_s[b];
    const int h = h0 + wid;
    #pragma unroll
    for (int ni = 0; ni < 4; ni++) {
        const int o0 = ni * 8 + 2 * tig;
        const float bs0 = g_bias[o0];
        const float bs1 = g_bias[o0 + 1];
        float* p0 = out + (((size_t)(b * COUT + o0) * DD + d) * HH_ + h) * WW;
        float* p1 = out + (((size_t)(b * COUT + o0 + 1) * DD + d) * HH_ + h) * WW;
        #pragma unroll
        for (int mi = 0; mi < 4; mi++) {
            const int w = mi * 16 + g;
            p0[w]     = sb * (acc[mi][ni][0] + bs0);
            p1[w]     = sb * (acc[mi][ni][1] + bs1);
            p0[w + 8] = sb * (acc[mi][ni][2] + bs0);
            p1[w + 8] = sb * (acc[mi][ni][3] + bs1);
        }
    }
}

extern "C" void kernel_launch(void* const* d_in, const int* in_sizes, int n_in,
                              void* d_out, int out_size) {
    // x: 16777216, rw: 64, weight: 221184, bias: 256
    const float *x = nullptr, *rw = nullptr, *wt = nullptr, *bi = nullptr;
    for (int i = 0; i < n_in; i++) {
        if (in_sizes[i] == 16777216)     x  = (const float*)d_in[i];
        else if (in_sizes[i] == 221184)  wt = (const float*)d_in[i];
        else if (in_sizes[i] == 256)     bi = (const float*)d_in[i];
        else if (in_sizes[i] == 64)      rw = (const float*)d_in[i];
    }
    float* out = (float*)d_out;

    cudaFuncSetAttribute(conv_kernel,
                         cudaFuncAttributeMaxDynamicSharedMemorySize,
                         SMEM_FLOATS * 4);

    prep_kernel<<<(W_FLOATS + 255) / 256, 256>>>(wt, bi, rw);

    dim3 grid(HH_ / TH, DD, B_);   // (8, 16, 8) = 1024 blocks
    conv_kernel<<<grid, 256, SMEM_FLOATS * 4>>>(x, out);
}